// round 16
// baseline (speedup 1.0000x reference)
#include <cuda_runtime.h>
#include <cuda_bf16.h>
#include <cuda_fp16.h>
#include <cstdint>

#define EMBED 4096
#define NTOK  8192
#define PDIM  64

// ---------------- device scratch (static; no cudaMalloc anywhere) ----------
__device__ __align__(16) float  g_x[NTOK * PDIM];
__device__ int    g_tok[NTOK];
__device__ int    g_count;
__device__ int    g_is64;
__device__ __align__(16) float  g_h  [(size_t)NTOK * EMBED];  // fp32 pre-LN
__device__ __align__(16) __half g_hf [(size_t)NTOK * EMBED];  // h fp16
__device__ __align__(16) __half g_w2f[(size_t)EMBED * EMBED]; // W2 fp16

__device__ __forceinline__ uint32_t smem_u32(const void* p) {
    uint32_t a;
    asm("{ .reg .u64 t; cvta.to.shared.u64 t, %1; cvt.u32.u64 %0, t; }" : "=r"(a) : "l"(p));
    return a;
}
__device__ __forceinline__ void cp16(uint32_t dst, const void* src) {
    asm volatile("cp.async.cg.shared.global [%0], [%1], 16;" :: "r"(dst), "l"(src) : "memory");
}
__device__ __forceinline__ void ldsm_x4(uint32_t* r, uint32_t a) {
    asm volatile("ldmatrix.sync.aligned.m8n8.x4.shared.b16 {%0,%1,%2,%3}, [%4];"
                 : "=r"(r[0]), "=r"(r[1]), "=r"(r[2]), "=r"(r[3]) : "r"(a));
}
__device__ __forceinline__ void mma_f16(float* c, const uint32_t* a, const uint32_t* b) {
    asm volatile(
        "mma.sync.aligned.m16n8k16.row.col.f32.f16.f16.f32 "
        "{%0,%1,%2,%3}, {%4,%5,%6,%7}, {%8,%9}, {%0,%1,%2,%3};"
        : "+f"(c[0]), "+f"(c[1]), "+f"(c[2]), "+f"(c[3])
        : "r"(a[0]), "r"(a[1]), "r"(a[2]), "r"(a[3]), "r"(b[0]), "r"(b[1]));
}

// ======================= K0: init + dtype detect ===========================
__global__ void k_init(const int* __restrict__ tp)
{
    __shared__ int odd_nz;
    if (threadIdx.x == 0) odd_nz = 0;
    __syncthreads();
    int local = 0;
    for (int i = threadIdx.x; i < NTOK; i += blockDim.x)
        if ((i & 1) && tp[i] != 0) local = 1;
    if (local) atomicOr(&odd_nz, 1);
    __syncthreads();
    if (threadIdx.x == 0) { g_is64 = (odd_nz == 0) ? 1 : 0; g_count = 0; }
}
__device__ __forceinline__ int load_type(const int* __restrict__ tp, int token) {
    return g_is64 ? tp[2 * token] : tp[token];
}

// ======================= K1a: compact polygon tokens =======================
__global__ void k_compact(const float* __restrict__ prompts, const int* __restrict__ tp)
{
    const int token = blockIdx.x * blockDim.x + threadIdx.x;
    if (token >= NTOK) return;
    if (load_type(tp, token) == 2) {
        const int s = atomicAdd(&g_count, 1);
        g_tok[s] = token;
        const float4* src = (const float4*)(prompts + (size_t)token * PDIM);
        float4* dst = (float4*)(g_x + (size_t)s * PDIM);
#pragma unroll
        for (int i = 0; i < PDIM / 4; i++) dst[i] = src[i];
    }
}

// ======================= K1b: point/box direct write =======================
__global__ void k_pointbox(const float* __restrict__ prompts, const int* __restrict__ tp,
                           const float* __restrict__ pw, const float* __restrict__ pb,
                           const float* __restrict__ bw, const float* __restrict__ bb,
                           const float* __restrict__ temb, float* __restrict__ out)
{
    const int token = blockIdx.x;
    const int tid   = threadIdx.x;
    const int t     = load_type(tp, token);
    const float* xp = prompts + (size_t)token * PDIM;
    if (t == 0) {
        const float x0 = xp[0], x1 = xp[1];
        const float2* pw2 = (const float2*)pw;
        float* op = out + (size_t)token * EMBED;
        for (int e = tid; e < EMBED; e += 128) {
            float2 w = pw2[e];
            op[e] = fmaf(w.x, x0, fmaf(w.y, x1, pb[e] + temb[e]));
        }
    } else if (t == 1) {
        const float x0 = xp[0], x1 = xp[1], x2 = xp[2], x3 = xp[3];
        const float4* bw4 = (const float4*)bw;
        float* op = out + (size_t)token * EMBED;
        for (int e = tid; e < EMBED; e += 128) {
            float4 w = bw4[e];
            float v = bb[e] + temb[EMBED + e];
            v = fmaf(w.x, x0, v); v = fmaf(w.y, x1, v);
            v = fmaf(w.z, x2, v); v = fmaf(w.w, x3, v);
            op[e] = v;
        }
    }
}

// ======================= K2a: GEMM1 h = W1 x + b1 (tiled, fp32) ============
__global__ __launch_bounds__(256) void k_poly_gemm(const float* __restrict__ w1,
                                                   const float* __restrict__ b1)
{
    const int count = g_count;
    const int m0 = blockIdx.y * 128;
    if (m0 >= count) return;
    const int e0 = blockIdx.x * 128;

    __shared__ __align__(16) float As[64][132];
    __shared__ __align__(16) float Bs[64][132];

    const int tid = threadIdx.x;
    for (int i = tid; i < 2048; i += 256) {
        const int row = i >> 4, q = i & 15;
        float4 v = *(const float4*)(g_x + (size_t)(m0 + row) * PDIM + q * 4);
        As[q*4+0][row] = v.x; As[q*4+1][row] = v.y;
        As[q*4+2][row] = v.z; As[q*4+3][row] = v.w;
    }
    for (int i = tid; i < 2048; i += 256) {
        const int row = i >> 4, q = i & 15;
        float4 v = *(const float4*)(w1 + (size_t)(e0 + row) * PDIM + q * 4);
        Bs[q*4+0][row] = v.x; Bs[q*4+1][row] = v.y;
        Bs[q*4+2][row] = v.z; Bs[q*4+3][row] = v.w;
    }
    __syncthreads();

    const int ty = tid >> 4, tx = tid & 15;
    float acc[8][8];
#pragma unroll
    for (int i = 0; i < 8; i++)
#pragma unroll
        for (int j = 0; j < 8; j++) acc[i][j] = 0.f;

#pragma unroll 4
    for (int k = 0; k < 64; k++) {
        float4 a0 = *(const float4*)&As[k][ty*8];
        float4 a1 = *(const float4*)&As[k][ty*8+4];
        float4 b0 = *(const float4*)&Bs[k][tx*8];
        float4 b1v = *(const float4*)&Bs[k][tx*8+4];
        float a[8] = {a0.x,a0.y,a0.z,a0.w,a1.x,a1.y,a1.z,a1.w};
        float b[8] = {b0.x,b0.y,b0.z,b0.w,b1v.x,b1v.y,b1v.z,b1v.w};
#pragma unroll
        for (int i = 0; i < 8; i++)
#pragma unroll
            for (int j = 0; j < 8; j++) acc[i][j] = fmaf(a[i], b[j], acc[i][j]);
    }

    float bias[8];
#pragma unroll
    for (int j = 0; j < 8; j++) bias[j] = b1[e0 + tx*8 + j];
#pragma unroll
    for (int i = 0; i < 8; i++) {
        const int m = m0 + ty*8 + i;
        if (m < count) {
            float* hp = g_h + (size_t)m * EMBED + e0 + tx*8;
            float4 v0 = make_float4(acc[i][0]+bias[0], acc[i][1]+bias[1],
                                    acc[i][2]+bias[2], acc[i][3]+bias[3]);
            float4 v1 = make_float4(acc[i][4]+bias[4], acc[i][5]+bias[5],
                                    acc[i][6]+bias[6], acc[i][7]+bias[7]);
            *(float4*)hp = v0; *(float4*)(hp+4) = v1;
        }
    }
}

// ======================= K2b: LN + ReLU + fp16 =============================
__global__ __launch_bounds__(256) void k_lnrelu(const float* __restrict__ gamma,
                                                const float* __restrict__ beta)
{
    const int m = blockIdx.x;
    if (m >= g_count) return;
    const int tid = threadIdx.x;
    const int e0  = tid * 16;

    float h[16];
    const float4* hp = (const float4*)(g_h + (size_t)m * EMBED + e0);
#pragma unroll
    for (int i = 0; i < 4; i++) {
        float4 v = hp[i];
        h[4*i] = v.x; h[4*i+1] = v.y; h[4*i+2] = v.z; h[4*i+3] = v.w;
    }
    float s = 0.f, sq = 0.f;
#pragma unroll
    for (int i = 0; i < 16; i++) { s += h[i]; sq = fmaf(h[i], h[i], sq); }
#pragma unroll
    for (int o = 16; o > 0; o >>= 1) {
        s  += __shfl_xor_sync(0xffffffffu, s,  o);
        sq += __shfl_xor_sync(0xffffffffu, sq, o);
    }
    __shared__ float ss[8], ssq[8], stat[2];
    const int wid = tid >> 5, lid = tid & 31;
    if (lid == 0) { ss[wid] = s; ssq[wid] = sq; }
    __syncthreads();
    if (tid == 0) {
        float S = 0.f, Q = 0.f;
#pragma unroll
        for (int i = 0; i < 8; i++) { S += ss[i]; Q += ssq[i]; }
        const float mu  = S * (1.f / EMBED);
        const float var = Q * (1.f / EMBED) - mu * mu;
        stat[0] = mu; stat[1] = rsqrtf(var + 1e-5f);
    }
    __syncthreads();
    const float mu = stat[0], inv = stat[1];
    __half2* hf = (__half2*)(g_hf + (size_t)m * EMBED + e0);
#pragma unroll
    for (int i = 0; i < 8; i++) {
        float v0 = fmaxf(fmaf((h[2*i]   - mu) * inv, gamma[e0 + 2*i],   beta[e0 + 2*i]),   0.f);
        float v1 = fmaxf(fmaf((h[2*i+1] - mu) * inv, gamma[e0 + 2*i+1], beta[e0 + 2*i+1]), 0.f);
        hf[i] = __floats2half2_rn(v0, v1);
    }
}

// ======================= K2c: W2 -> fp16 ===================================
__global__ __launch_bounds__(256) void k_cvt_w2(const float* __restrict__ w2)
{
    const size_t N4 = (size_t)EMBED * EMBED / 4;
    __half2* dst = (__half2*)g_w2f;
    for (size_t i = (size_t)blockIdx.x * 256 + threadIdx.x; i < N4;
         i += (size_t)gridDim.x * 256) {
        float4 v = ((const float4*)w2)[i];
        dst[2*i]   = __floats2half2_rn(v.x, v.y);
        dst[2*i+1] = __floats2half2_rn(v.z, v.w);
    }
}

// ======================= K3: GEMM2 via ldmatrix + mma.f16 (3-stage) ========
// CTA 128x128, 8 warps (2x4), warp tile 64x32. K chunk = 32 fp16 (64B rows).
// Per stage: A [128][32] + B [128][32] = 16KB. 3 stages = 48KB -> 2 CTA/SM.
// Swizzle: 16B chunk ^= (row>>1)&3. One __syncthreads per chunk.
// B fragments loaded PAIRWISE via ldsm_x4 (2 issues for 4 n-frags) -> 6 LDSM/kf.
#define TILE_B   8192
#define STAGE_B  16384
#define NSTG     3
#define NCH      (EMBED / 32)   // 128

__global__ __launch_bounds__(256, 2) void k_gemm2_mma(const float* __restrict__ b2,
                                                      const float* __restrict__ temb,
                                                      float* __restrict__ out)
{
    const int count = g_count;
    const int m0 = blockIdx.y * 128;
    if (m0 >= count) return;
    const int n0 = blockIdx.x * 128;

    extern __shared__ char smem[];
    const uint32_t sb = smem_u32(smem);

    const int tid  = threadIdx.x;
    const int wid  = tid >> 5, lane = tid & 31;
    const int warp_m = wid >> 2, warp_n = wid & 3;

    const __half* srcs[2] = { g_hf  + (size_t)m0 * EMBED,
                              g_w2f + (size_t)n0 * EMBED };

    auto stage_load = [&](int kc, int s) {
        const uint32_t stb = sb + s * STAGE_B;
#pragma unroll
        for (int t = 0; t < 4; t++) {
            const int tile   = t >> 1;
            const int within = ((t & 1) << 8) + tid;   // 0..511
            const int row    = within >> 2;
            const int c4     = within & 3;
            const uint32_t dst = stb + tile * TILE_B + row * 64
                               + (((c4 ^ ((row >> 1) & 3))) << 4);
            cp16(dst, srcs[tile] + (size_t)row * EMBED + kc * 32 + c4 * 8);
        }
        asm volatile("cp.async.commit_group;" ::: "memory");
    };

    float acc[4][4][4];
#pragma unroll
    for (int i = 0; i < 4; i++)
#pragma unroll
        for (int j = 0; j < 4; j++)
#pragma unroll
            for (int v = 0; v < 4; v++) acc[i][j][v] = 0.f;

    // ldmatrix lane geometry
    const int a_r    = (lane & 7) + ((lane >> 3) & 1) * 8;  // row within 16-frag
    const int a_kh   = (lane >> 4) & 1;                     // k-half select
    const int b_r    = lane & 7;
    const int b_half = (lane >> 3) & 1;                     // k-half select
    const int b_pair = (lane >> 4) & 1;                     // odd n-frag of pair

    stage_load(0, 0);
    stage_load(1, 1);

    for (int kc = 0; kc < NCH; kc++) {
        const int s = kc % NSTG;
        if (kc + 1 < NCH) {
            asm volatile("cp.async.wait_group 1;" ::: "memory");  // group kc done
        } else {
            asm volatile("cp.async.wait_group 0;" ::: "memory");
        }
        __syncthreads();   // data visible; all warps done with chunk kc-1

        if (kc + 2 < NCH) stage_load(kc + 2, (kc + 2) % NSTG);  // buffer of kc-1

        const uint32_t tA = sb + s * STAGE_B;
        const uint32_t tB = tA + TILE_B;

#pragma unroll
        for (int kf = 0; kf < 2; kf++) {
            uint32_t af[4][4], bf[4][2];
#pragma unroll
            for (int mf = 0; mf < 4; mf++) {
                const int row = warp_m * 64 + mf * 16 + a_r;
                const int ch  = (kf * 2 + a_kh) ^ ((row >> 1) & 3);
                ldsm_x4(af[mf], tA + row * 64 + (ch << 4));
            }
#pragma unroll
            for (int nfp = 0; nfp < 2; nfp++) {
                uint32_t bq[4];
                const int row = warp_n * 32 + nfp * 16 + b_pair * 8 + b_r;
                const int ch  = (kf * 2 + b_half) ^ ((row >> 1) & 3);
                ldsm_x4(bq, tB + row * 64 + (ch << 4));
                bf[2*nfp][0]   = bq[0]; bf[2*nfp][1]   = bq[1];
                bf[2*nfp+1][0] = bq[2]; bf[2*nfp+1][1] = bq[3];
            }
#pragma unroll
            for (int mf = 0; mf < 4; mf++)
#pragma unroll
                for (int nf = 0; nf < 4; nf++)
                    mma_f16(acc[mf][nf], af[mf], bf[nf]);
        }
    }

    // epilogue: bias + type_emb, scatter rows via g_tok
    const int g = lane >> 2, t2 = (lane & 3) * 2;
    float bias[4][2];
#pragma unroll
    for (int nf = 0; nf < 4; nf++) {
        const int nb = n0 + warp_n * 32 + nf * 8 + t2;
        bias[nf][0] = b2[nb]     + temb[2 * EMBED + nb];
        bias[nf][1] = b2[nb + 1] + temb[2 * EMBED + nb + 1];
    }
#pragma unroll
    for (int mf = 0; mf < 4; mf++) {
        const int mr0 = m0 + warp_m * 64 + mf * 16 + g;
        const int mr1 = mr0 + 8;
        const bool v0 = mr0 < count, v1 = mr1 < count;
        float* op0 = v0 ? out + (size_t)g_tok[mr0] * EMBED : nullptr;
        float* op1 = v1 ? out + (size_t)g_tok[mr1] * EMBED : nullptr;
#pragma unroll
        for (int nf = 0; nf < 4; nf++) {
            const int nb = n0 + warp_n * 32 + nf * 8 + t2;
            if (v0) *(float2*)(op0 + nb) =
                make_float2(acc[mf][nf][0] + bias[nf][0], acc[mf][nf][1] + bias[nf][1]);
            if (v1) *(float2*)(op1 + nb) =
                make_float2(acc[mf][nf][2] + bias[nf][0], acc[mf][nf][3] + bias[nf][1]);
        }
    }
}

// ======================= launch ============================================
extern "C" void kernel_launch(void* const* d_in, const int* in_sizes, int n_in,
                              void* d_out, int out_size)
{
    const float* prompts = (const float*)d_in[0];
    const int*   types   = (const int*)d_in[1];
    const float* point_w = (const float*)d_in[2];
    const float* point_b = (const float*)d_in[3];
    const float* box_w   = (const float*)d_in[4];
    const float* box_b   = (const float*)d_in[5];
    const float* poly_w1 = (const float*)d_in[6];
    const float* poly_b1 = (const float*)d_in[7];
    const float* ln_g    = (const float*)d_in[8];
    const float* ln_b    = (const float*)d_in[9];
    const float* poly_w2 = (const float*)d_in[10];
    const float* poly_b2 = (const float*)d_in[11];
    const float* temb    = (const float*)d_in[12];
    float* out = (float*)d_out;

    static cudaStream_t s1 = nullptr, s2 = nullptr;
    static cudaEvent_t  e0, e1, e2;
    if (!s1) {
        cudaStreamCreateWithFlags(&s1, cudaStreamNonBlocking);
        cudaStreamCreateWithFlags(&s2, cudaStreamNonBlocking);
        cudaEventCreateWithFlags(&e0, cudaEventDisableTiming);
        cudaEventCreateWithFlags(&e1, cudaEventDisableTiming);
        cudaEventCreateWithFlags(&e2, cudaEventDisableTiming);
        cudaFuncSetAttribute(k_gemm2_mma, cudaFuncAttributeMaxDynamicSharedMemorySize,
                             NSTG * STAGE_B);
    }

    // main stream: init -> compact -> poly_gemm -> lnrelu
    k_init<<<1, 256>>>(types);
    cudaEventRecord(e0, 0);

    // fork: pointbox and cvt_w2 off the critical path
    cudaStreamWaitEvent(s1, e0, 0);
    k_pointbox<<<NTOK, 128, 0, s1>>>(prompts, types, point_w, point_b,
                                     box_w, box_b, temb, out);
    cudaEventRecord(e1, s1);

    cudaStreamWaitEvent(s2, e0, 0);
    k_cvt_w2<<<2048, 256, 0, s2>>>(poly_w2);
    cudaEventRecord(e2, s2);

    k_compact<<<NTOK / 256, 256>>>(prompts, types);
    {
        dim3 g1(EMBED / 128, NTOK / 128);   // early exit past count
        k_poly_gemm<<<g1, 256>>>(poly_w1, poly_b1);
    }
    k_lnrelu<<<NTOK, 256>>>(ln_g, ln_b);

    // join and run the big GEMM
    cudaStreamWaitEvent(0, e1, 0);
    cudaStreamWaitEvent(0, e2, 0);
    {
        dim3 g2(EMBED / 128, NTOK / 128);   // early exit past count
        k_gemm2_mma<<<g2, 256, NSTG * STAGE_B>>>(poly_b2, temb, out);
    }
}

// round 17
// speedup vs baseline: 1.1061x; 1.1061x over previous
#include <cuda_runtime.h>
#include <cuda_bf16.h>
#include <cuda_fp16.h>
#include <cstdint>

#define EMBED 4096
#define NTOK  8192
#define PDIM  64

// ---------------- device scratch (static; no cudaMalloc anywhere) ----------
__device__ __align__(16) float  g_x[NTOK * PDIM];
__device__ int    g_tok[NTOK];
__device__ int    g_count;
__device__ int    g_is64;
__device__ __align__(16) float  g_h  [(size_t)NTOK * EMBED];  // fp32 pre-LN
__device__ __align__(16) __half g_hf [(size_t)NTOK * EMBED];  // h fp16
__device__ __align__(16) __half g_w2f[(size_t)EMBED * EMBED]; // W2 fp16

__device__ __forceinline__ uint32_t smem_u32(const void* p) {
    uint32_t a;
    asm("{ .reg .u64 t; cvta.to.shared.u64 t, %1; cvt.u32.u64 %0, t; }" : "=r"(a) : "l"(p));
    return a;
}
__device__ __forceinline__ void cp16(uint32_t dst, const void* src) {
    asm volatile("cp.async.cg.shared.global [%0], [%1], 16;" :: "r"(dst), "l"(src) : "memory");
}
__device__ __forceinline__ void ldsm_x4(uint32_t* r, uint32_t a) {
    asm volatile("ldmatrix.sync.aligned.m8n8.x4.shared.b16 {%0,%1,%2,%3}, [%4];"
                 : "=r"(r[0]), "=r"(r[1]), "=r"(r[2]), "=r"(r[3]) : "r"(a));
}
__device__ __forceinline__ void mma_f16(float* c, const uint32_t* a, const uint32_t* b) {
    asm volatile(
        "mma.sync.aligned.m16n8k16.row.col.f32.f16.f16.f32 "
        "{%0,%1,%2,%3}, {%4,%5,%6,%7}, {%8,%9}, {%0,%1,%2,%3};"
        : "+f"(c[0]), "+f"(c[1]), "+f"(c[2]), "+f"(c[3])
        : "r"(a[0]), "r"(a[1]), "r"(a[2]), "r"(a[3]), "r"(b[0]), "r"(b[1]));
}

// ======================= K0: init + dtype detect ===========================
__global__ void k_init(const int* __restrict__ tp)
{
    __shared__ int odd_nz;
    if (threadIdx.x == 0) odd_nz = 0;
    __syncthreads();
    int local = 0;
    for (int i = threadIdx.x; i < NTOK; i += blockDim.x)
        if ((i & 1) && tp[i] != 0) local = 1;
    if (local) atomicOr(&odd_nz, 1);
    __syncthreads();
    if (threadIdx.x == 0) { g_is64 = (odd_nz == 0) ? 1 : 0; g_count = 0; }
}
__device__ __forceinline__ int load_type(const int* __restrict__ tp, int token) {
    return g_is64 ? tp[2 * token] : tp[token];
}

// ======================= K1a: compact polygon tokens =======================
__global__ void k_compact(const float* __restrict__ prompts, const int* __restrict__ tp)
{
    const int token = blockIdx.x * blockDim.x + threadIdx.x;
    if (token >= NTOK) return;
    if (load_type(tp, token) == 2) {
        const int s = atomicAdd(&g_count, 1);
        g_tok[s] = token;
        const float4* src = (const float4*)(prompts + (size_t)token * PDIM);
        float4* dst = (float4*)(g_x + (size_t)s * PDIM);
#pragma unroll
        for (int i = 0; i < PDIM / 4; i++) dst[i] = src[i];
    }
}

// ======================= K1b: point/box direct write =======================
__global__ void k_pointbox(const float* __restrict__ prompts, const int* __restrict__ tp,
                           const float* __restrict__ pw, const float* __restrict__ pb,
                           const float* __restrict__ bw, const float* __restrict__ bb,
                           const float* __restrict__ temb, float* __restrict__ out)
{
    const int token = blockIdx.x;
    const int tid   = threadIdx.x;
    const int t     = load_type(tp, token);
    const float* xp = prompts + (size_t)token * PDIM;
    if (t == 0) {
        const float x0 = xp[0], x1 = xp[1];
        const float2* pw2 = (const float2*)pw;
        float* op = out + (size_t)token * EMBED;
        for (int e = tid; e < EMBED; e += 128) {
            float2 w = pw2[e];
            op[e] = fmaf(w.x, x0, fmaf(w.y, x1, pb[e] + temb[e]));
        }
    } else if (t == 1) {
        const float x0 = xp[0], x1 = xp[1], x2 = xp[2], x3 = xp[3];
        const float4* bw4 = (const float4*)bw;
        float* op = out + (size_t)token * EMBED;
        for (int e = tid; e < EMBED; e += 128) {
            float4 w = bw4[e];
            float v = bb[e] + temb[EMBED + e];
            v = fmaf(w.x, x0, v); v = fmaf(w.y, x1, v);
            v = fmaf(w.z, x2, v); v = fmaf(w.w, x3, v);
            op[e] = v;
        }
    }
}

// ======================= K2a: GEMM1 h = W1 x + b1 (tiled, fp32) ============
__global__ __launch_bounds__(256) void k_poly_gemm(const float* __restrict__ w1,
                                                   const float* __restrict__ b1)
{
    const int count = g_count;
    const int m0 = blockIdx.y * 128;
    if (m0 >= count) return;
    const int e0 = blockIdx.x * 128;

    __shared__ __align__(16) float As[64][132];
    __shared__ __align__(16) float Bs[64][132];

    const int tid = threadIdx.x;
    for (int i = tid; i < 2048; i += 256) {
        const int row = i >> 4, q = i & 15;
        float4 v = *(const float4*)(g_x + (size_t)(m0 + row) * PDIM + q * 4);
        As[q*4+0][row] = v.x; As[q*4+1][row] = v.y;
        As[q*4+2][row] = v.z; As[q*4+3][row] = v.w;
    }
    for (int i = tid; i < 2048; i += 256) {
        const int row = i >> 4, q = i & 15;
        float4 v = *(const float4*)(w1 + (size_t)(e0 + row) * PDIM + q * 4);
        Bs[q*4+0][row] = v.x; Bs[q*4+1][row] = v.y;
        Bs[q*4+2][row] = v.z; Bs[q*4+3][row] = v.w;
    }
    __syncthreads();

    const int ty = tid >> 4, tx = tid & 15;
    float acc[8][8];
#pragma unroll
    for (int i = 0; i < 8; i++)
#pragma unroll
        for (int j = 0; j < 8; j++) acc[i][j] = 0.f;

#pragma unroll 4
    for (int k = 0; k < 64; k++) {
        float4 a0 = *(const float4*)&As[k][ty*8];
        float4 a1 = *(const float4*)&As[k][ty*8+4];
        float4 b0 = *(const float4*)&Bs[k][tx*8];
        float4 b1v = *(const float4*)&Bs[k][tx*8+4];
        float a[8] = {a0.x,a0.y,a0.z,a0.w,a1.x,a1.y,a1.z,a1.w};
        float b[8] = {b0.x,b0.y,b0.z,b0.w,b1v.x,b1v.y,b1v.z,b1v.w};
#pragma unroll
        for (int i = 0; i < 8; i++)
#pragma unroll
            for (int j = 0; j < 8; j++) acc[i][j] = fmaf(a[i], b[j], acc[i][j]);
    }

    float bias[8];
#pragma unroll
    for (int j = 0; j < 8; j++) bias[j] = b1[e0 + tx*8 + j];
#pragma unroll
    for (int i = 0; i < 8; i++) {
        const int m = m0 + ty*8 + i;
        if (m < count) {
            float* hp = g_h + (size_t)m * EMBED + e0 + tx*8;
            float4 v0 = make_float4(acc[i][0]+bias[0], acc[i][1]+bias[1],
                                    acc[i][2]+bias[2], acc[i][3]+bias[3]);
            float4 v1 = make_float4(acc[i][4]+bias[4], acc[i][5]+bias[5],
                                    acc[i][6]+bias[6], acc[i][7]+bias[7]);
            *(float4*)hp = v0; *(float4*)(hp+4) = v1;
        }
    }
}

// ======================= K2b: LN + ReLU + fp16 =============================
__global__ __launch_bounds__(256) void k_lnrelu(const float* __restrict__ gamma,
                                                const float* __restrict__ beta)
{
    const int m = blockIdx.x;
    if (m >= g_count) return;
    const int tid = threadIdx.x;
    const int e0  = tid * 16;

    float h[16];
    const float4* hp = (const float4*)(g_h + (size_t)m * EMBED + e0);
#pragma unroll
    for (int i = 0; i < 4; i++) {
        float4 v = hp[i];
        h[4*i] = v.x; h[4*i+1] = v.y; h[4*i+2] = v.z; h[4*i+3] = v.w;
    }
    float s = 0.f, sq = 0.f;
#pragma unroll
    for (int i = 0; i < 16; i++) { s += h[i]; sq = fmaf(h[i], h[i], sq); }
#pragma unroll
    for (int o = 16; o > 0; o >>= 1) {
        s  += __shfl_xor_sync(0xffffffffu, s,  o);
        sq += __shfl_xor_sync(0xffffffffu, sq, o);
    }
    __shared__ float ss[8], ssq[8], stat[2];
    const int wid = tid >> 5, lid = tid & 31;
    if (lid == 0) { ss[wid] = s; ssq[wid] = sq; }
    __syncthreads();
    if (tid == 0) {
        float S = 0.f, Q = 0.f;
#pragma unroll
        for (int i = 0; i < 8; i++) { S += ss[i]; Q += ssq[i]; }
        const float mu  = S * (1.f / EMBED);
        const float var = Q * (1.f / EMBED) - mu * mu;
        stat[0] = mu; stat[1] = rsqrtf(var + 1e-5f);
    }
    __syncthreads();
    const float mu = stat[0], inv = stat[1];
    __half2* hf = (__half2*)(g_hf + (size_t)m * EMBED + e0);
#pragma unroll
    for (int i = 0; i < 8; i++) {
        float v0 = fmaxf(fmaf((h[2*i]   - mu) * inv, gamma[e0 + 2*i],   beta[e0 + 2*i]),   0.f);
        float v1 = fmaxf(fmaf((h[2*i+1] - mu) * inv, gamma[e0 + 2*i+1], beta[e0 + 2*i+1]), 0.f);
        hf[i] = __floats2half2_rn(v0, v1);
    }
}

// ======================= K2c: W2 -> fp16 ===================================
__global__ __launch_bounds__(256) void k_cvt_w2(const float* __restrict__ w2)
{
    const size_t N4 = (size_t)EMBED * EMBED / 4;
    __half2* dst = (__half2*)g_w2f;
    for (size_t i = (size_t)blockIdx.x * 256 + threadIdx.x; i < N4;
         i += (size_t)gridDim.x * 256) {
        float4 v = ((const float4*)w2)[i];
        dst[2*i]   = __floats2half2_rn(v.x, v.y);
        dst[2*i+1] = __floats2half2_rn(v.z, v.w);
    }
}

// ======================= K3: GEMM2 via ldmatrix + mma.f16 ==================
// CTA 128x128, 8 warps (2x4), warp tile 64x32. K chunk = 64 fp16 (128B rows).
// Per stage: A [128][64] + B [128][64] = 32KB. 3 stages = 96KB -> 2 CTA/SM.
// Swizzle: 16B chunk ^= row & 7 (8 chunks per 128B row). 4 kf per chunk ->
// long unrolled mma runs between stage switches (64 barriers total).
#define TILE_B   16384
#define STAGE_B  32768
#define NSTG     3
#define KCH      64
#define NCH      (EMBED / KCH)   // 64

__global__ __launch_bounds__(256, 2) void k_gemm2_mma(const float* __restrict__ b2,
                                                      const float* __restrict__ temb,
                                                      float* __restrict__ out)
{
    const int count = g_count;
    const int m0 = blockIdx.y * 128;
    if (m0 >= count) return;
    const int n0 = blockIdx.x * 128;

    extern __shared__ char smem[];
    const uint32_t sb = smem_u32(smem);

    const int tid  = threadIdx.x;
    const int wid  = tid >> 5, lane = tid & 31;
    const int warp_m = wid >> 2, warp_n = wid & 3;

    const __half* srcs[2] = { g_hf  + (size_t)m0 * EMBED,
                              g_w2f + (size_t)n0 * EMBED };

    auto stage_load = [&](int kc, int s) {
        const uint32_t stb = sb + s * STAGE_B;
#pragma unroll
        for (int t = 0; t < 8; t++) {
            const int tile   = t >> 2;                 // 0=A, 1=B
            const int within = (t & 3) * 256 + tid;    // 0..1023
            const int row    = within >> 3;
            const int ch     = within & 7;
            const uint32_t dst = stb + tile * TILE_B + row * 128
                               + ((ch ^ (row & 7)) << 4);
            cp16(dst, srcs[tile] + (size_t)row * EMBED + kc * KCH + ch * 8);
        }
        asm volatile("cp.async.commit_group;" ::: "memory");
    };

    float acc[4][4][4];
#pragma unroll
    for (int i = 0; i < 4; i++)
#pragma unroll
        for (int j = 0; j < 4; j++)
#pragma unroll
            for (int v = 0; v < 4; v++) acc[i][j][v] = 0.f;

    // ldmatrix lane geometry (validated in R13 on 128B-row swizzle)
    const int a_r    = (lane & 7) + ((lane >> 3) & 1) * 8;  // row within 16-frag
    const int a_kh   = (lane >> 4) & 1;                     // k-half select
    const int b_r    = lane & 7;
    const int b_half = (lane >> 3) & 1;                     // k-half select
    const int b_pair = (lane >> 4) & 1;                     // odd n-frag of pair

    stage_load(0, 0);
    stage_load(1, 1);

    for (int kc = 0; kc < NCH; kc++) {
        const int s = kc % NSTG;
        if (kc + 1 < NCH) {
            asm volatile("cp.async.wait_group 1;" ::: "memory");  // group kc done
        } else {
            asm volatile("cp.async.wait_group 0;" ::: "memory");
        }
        __syncthreads();   // data visible; all warps done with chunk kc-1

        if (kc + 2 < NCH) stage_load(kc + 2, (kc + 2) % NSTG);  // buffer of kc-1

        const uint32_t tA = sb + s * STAGE_B;
        const uint32_t tB = tA + TILE_B;

#pragma unroll
        for (int kf = 0; kf < 4; kf++) {
            uint32_t af[4][4], bf[4][2];
#pragma unroll
            for (int mf = 0; mf < 4; mf++) {
                const int row = warp_m * 64 + mf * 16 + a_r;
                const int ch  = (kf * 2 + a_kh) ^ (row & 7);
                ldsm_x4(af[mf], tA + row * 128 + (ch << 4));
            }
#pragma unroll
            for (int nfp = 0; nfp < 2; nfp++) {
                uint32_t bq[4];
                const int row = warp_n * 32 + nfp * 16 + b_pair * 8 + b_r;
                const int ch  = (kf * 2 + b_half) ^ (row & 7);
                ldsm_x4(bq, tB + row * 128 + (ch << 4));
                bf[2*nfp][0]   = bq[0]; bf[2*nfp][1]   = bq[1];
                bf[2*nfp+1][0] = bq[2]; bf[2*nfp+1][1] = bq[3];
            }
#pragma unroll
            for (int mf = 0; mf < 4; mf++)
#pragma unroll
                for (int nf = 0; nf < 4; nf++)
                    mma_f16(acc[mf][nf], af[mf], bf[nf]);
        }
    }

    // epilogue: bias + type_emb, scatter rows via g_tok
    const int g = lane >> 2, t2 = (lane & 3) * 2;
    float bias[4][2];
#pragma unroll
    for (int nf = 0; nf < 4; nf++) {
        const int nb = n0 + warp_n * 32 + nf * 8 + t2;
        bias[nf][0] = b2[nb]     + temb[2 * EMBED + nb];
        bias[nf][1] = b2[nb + 1] + temb[2 * EMBED + nb + 1];
    }
#pragma unroll
    for (int mf = 0; mf < 4; mf++) {
        const int mr0 = m0 + warp_m * 64 + mf * 16 + g;
        const int mr1 = mr0 + 8;
        const bool v0 = mr0 < count, v1 = mr1 < count;
        float* op0 = v0 ? out + (size_t)g_tok[mr0] * EMBED : nullptr;
        float* op1 = v1 ? out + (size_t)g_tok[mr1] * EMBED : nullptr;
#pragma unroll
        for (int nf = 0; nf < 4; nf++) {
            const int nb = n0 + warp_n * 32 + nf * 8 + t2;
            if (v0) *(float2*)(op0 + nb) =
                make_float2(acc[mf][nf][0] + bias[nf][0], acc[mf][nf][1] + bias[nf][1]);
            if (v1) *(float2*)(op1 + nb) =
                make_float2(acc[mf][nf][2] + bias[nf][0], acc[mf][nf][3] + bias[nf][1]);
        }
    }
}

// ======================= launch ============================================
extern "C" void kernel_launch(void* const* d_in, const int* in_sizes, int n_in,
                              void* d_out, int out_size)
{
    const float* prompts = (const float*)d_in[0];
    const int*   types   = (const int*)d_in[1];
    const float* point_w = (const float*)d_in[2];
    const float* point_b = (const float*)d_in[3];
    const float* box_w   = (const float*)d_in[4];
    const float* box_b   = (const float*)d_in[5];
    const float* poly_w1 = (const float*)d_in[6];
    const float* poly_b1 = (const float*)d_in[7];
    const float* ln_g    = (const float*)d_in[8];
    const float* ln_b    = (const float*)d_in[9];
    const float* poly_w2 = (const float*)d_in[10];
    const float* poly_b2 = (const float*)d_in[11];
    const float* temb    = (const float*)d_in[12];
    float* out = (float*)d_out;

    static cudaStream_t s1 = nullptr, s2 = nullptr;
    static cudaEvent_t  e0, e1, e2;
    if (!s1) {
        cudaStreamCreateWithFlags(&s1, cudaStreamNonBlocking);
        cudaStreamCreateWithFlags(&s2, cudaStreamNonBlocking);
        cudaEventCreateWithFlags(&e0, cudaEventDisableTiming);
        cudaEventCreateWithFlags(&e1, cudaEventDisableTiming);
        cudaEventCreateWithFlags(&e2, cudaEventDisableTiming);
        cudaFuncSetAttribute(k_gemm2_mma, cudaFuncAttributeMaxDynamicSharedMemorySize,
                             NSTG * STAGE_B);
    }

    // main stream: init -> compact -> poly_gemm -> lnrelu
    k_init<<<1, 256>>>(types);
    cudaEventRecord(e0, 0);

    // fork: pointbox and cvt_w2 off the critical path
    cudaStreamWaitEvent(s1, e0, 0);
    k_pointbox<<<NTOK, 128, 0, s1>>>(prompts, types, point_w, point_b,
                                     box_w, box_b, temb, out);
    cudaEventRecord(e1, s1);

    cudaStreamWaitEvent(s2, e0, 0);
    k_cvt_w2<<<2048, 256, 0, s2>>>(poly_w2);
    cudaEventRecord(e2, s2);

    k_compact<<<NTOK / 256, 256>>>(prompts, types);
    {
        dim3 g1(EMBED / 128, NTOK / 128);   // early exit past count
        k_poly_gemm<<<g1, 256>>>(poly_w1, poly_b1);
    }
    k_lnrelu<<<NTOK, 256>>>(ln_g, ln_b);

    // join and run the big GEMM
    cudaStreamWaitEvent(0, e1, 0);
    cudaStreamWaitEvent(0, e2, 0);
    {
        dim3 g2(EMBED / 128, NTOK / 128);   // early exit past count
        k_gemm2_mma<<<g2, 256, NSTG * STAGE_B>>>(poly_b2, temb, out);
    }
}